// round 1
// baseline (speedup 1.0000x reference)
#include <cuda_runtime.h>
#include <cuda_bf16.h>

#define NPIX (8*128*128)   // 131072 pixels
#define CCH  64

// Scratch (device globals; no allocations). All NHWC: [n][y][x][c], c contiguous.
__device__ float g_bufA[(size_t)NPIX*CCH];
__device__ float g_bufB[(size_t)NPIX*CCH];
__device__ float g_q[(size_t)NPIX*CCH];
__device__ float g_k[(size_t)NPIX*CCH];
__device__ float g_v[(size_t)NPIX*CCH];

__device__ __forceinline__ float dot4(float4 a, float4 b) {
    return a.x*b.x + a.y*b.y + a.z*b.z + a.w*b.w;
}

// ---------------------------------------------------------------------------
// conv_in: x NCHW [8,3,128,128] -> relu(conv3x3) -> out NHWC [8,128,128,64]
// thread = (pixel, quarter of 16 outputs). 256 thr = 64 pixels.
// ---------------------------------------------------------------------------
__global__ __launch_bounds__(256) void conv_in_k(const float* __restrict__ x,
                                                 const float* __restrict__ w,
                                                 float* __restrict__ out) {
    __shared__ float ws[64*27];     // [o][c*9+dy*3+dx] -- matches OIHW layout directly
    int tid = threadIdx.x;
    for (int i = tid; i < 64*27; i += 256) ws[i] = w[i];
    __syncthreads();

    int pix = blockIdx.x*64 + (tid >> 2);
    int q   = tid & 3;
    int n = pix >> 14, rem = pix & 16383, y = rem >> 7, xx = rem & 127;

    float v[27];
    int t = 0;
    #pragma unroll
    for (int c = 0; c < 3; c++)
        #pragma unroll
        for (int dy = 0; dy < 3; dy++)
            #pragma unroll
            for (int dx = 0; dx < 3; dx++, t++) {
                int yy = y + dy - 1, xv = xx + dx - 1;
                bool ok = (yy >= 0) & (yy < 128) & (xv >= 0) & (xv < 128);
                v[t] = ok ? x[((n*3 + c) << 14) + (yy << 7) + xv] : 0.f;
            }

    float r[16];
    #pragma unroll
    for (int j = 0; j < 16; j++) {
        int o = q*16 + j;
        float acc = 0.f;
        #pragma unroll
        for (int tt = 0; tt < 27; tt++) acc = fmaf(v[tt], ws[o*27 + tt], acc);
        r[j] = fmaxf(acc, 0.f);
    }
    float4* dst = (float4*)(out + (size_t)pix*64 + q*16);
    dst[0] = make_float4(r[0], r[1], r[2], r[3]);
    dst[1] = make_float4(r[4], r[5], r[6], r[7]);
    dst[2] = make_float4(r[8], r[9], r[10], r[11]);
    dst[3] = make_float4(r[12], r[13], r[14], r[15]);
}

// ---------------------------------------------------------------------------
// qkv: fused triple 1x1 conv. in NHWC -> q,k,v NHWC.
// Block: 64 pixels x 192 outputs. Thread tile: 4 pixels x 12 outputs.
// Weights stored transposed in smem [c][o] (192 wide) for float4 reads.
// ---------------------------------------------------------------------------
__global__ __launch_bounds__(256) void qkv_k(const float* __restrict__ in,
                                             const float* __restrict__ w1,
                                             const float* __restrict__ w2,
                                             const float* __restrict__ w3,
                                             float* __restrict__ qo,
                                             float* __restrict__ ko,
                                             float* __restrict__ vo) {
    extern __shared__ float sm[];
    float* in_s = sm;            // 64*64
    float* w_s  = sm + 64*64;    // 64*192, [c][o]
    int tid = threadIdx.x;
    size_t pix0 = (size_t)blockIdx.x * 64;

    const float4* src = (const float4*)(in + pix0*64);
    float4* d4 = (float4*)in_s;
    #pragma unroll
    for (int i = 0; i < 4; i++) d4[tid + 256*i] = src[tid + 256*i];

    for (int idx = tid; idx < 64*192; idx += 256) {
        int c = idx / 192, o = idx % 192;
        float val = (o < 64) ? w1[o*64 + c]
                  : (o < 128) ? w2[(o-64)*64 + c]
                              : w3[(o-128)*64 + c];
        w_s[c*192 + o] = val;
    }
    __syncthreads();

    int ox = tid & 15, py = tid >> 4;
    int o0 = ox*12, p0 = py*4;
    float acc[4][12];
    #pragma unroll
    for (int p = 0; p < 4; p++)
        #pragma unroll
        for (int j = 0; j < 12; j++) acc[p][j] = 0.f;

    #pragma unroll 4
    for (int c = 0; c < 64; c++) {
        float a0 = in_s[(p0+0)*64 + c];
        float a1 = in_s[(p0+1)*64 + c];
        float a2 = in_s[(p0+2)*64 + c];
        float a3 = in_s[(p0+3)*64 + c];
        float4 b0 = *(const float4*)&w_s[c*192 + o0 + 0];
        float4 b1 = *(const float4*)&w_s[c*192 + o0 + 4];
        float4 b2 = *(const float4*)&w_s[c*192 + o0 + 8];
        float b[12] = {b0.x,b0.y,b0.z,b0.w, b1.x,b1.y,b1.z,b1.w, b2.x,b2.y,b2.z,b2.w};
        #pragma unroll
        for (int j = 0; j < 12; j++) {
            acc[0][j] = fmaf(a0, b[j], acc[0][j]);
            acc[1][j] = fmaf(a1, b[j], acc[1][j]);
            acc[2][j] = fmaf(a2, b[j], acc[2][j]);
            acc[3][j] = fmaf(a3, b[j], acc[3][j]);
        }
    }

    #pragma unroll
    for (int p = 0; p < 4; p++) {
        size_t pix = pix0 + p0 + p;
        #pragma unroll
        for (int j = 0; j < 12; j++) {
            int o = o0 + j;
            float val = acc[p][j];
            if (o < 64)       qo[pix*64 + o]        = val;
            else if (o < 128) ko[pix*64 + (o-64)]   = val;
            else              vo[pix*64 + (o-128)]  = val;
        }
    }
}

// ---------------------------------------------------------------------------
// attn: 5x5 local attention + relu. q,k,v NHWC -> out NHWC.
// Block = 8x8 pixel tile (one n). K/V halo 12x12 in smem, rows padded to 68.
// 4 threads per pixel (channel quarters); shuffle-reduce the 25 dots.
// ---------------------------------------------------------------------------
__global__ __launch_bounds__(256) void attn_k(const float* __restrict__ xq,
                                              const float* __restrict__ xk,
                                              const float* __restrict__ xv,
                                              float* __restrict__ out) {
    extern __shared__ float sm[];
    float* q_s = sm;                    // 64*68
    float* k_s = sm + 64*68;            // 144*68
    float* v_s = k_s + 144*68;          // 144*68
    int tid = threadIdx.x;
    int bx = blockIdx.x, by = blockIdx.y, n = blockIdx.z;
    int y0 = by*8, x0 = bx*8;

    // q tile: 64 px * 16 float4
    for (int idx = tid; idx < 64*16; idx += 256) {
        int hp = idx >> 4, c4 = idx & 15;
        int yy = y0 + (hp >> 3), xx = x0 + (hp & 7);
        float4 val = ((const float4*)(xq + (((size_t)n << 14) + (yy << 7) + xx)*64))[c4];
        ((float4*)(q_s + hp*68))[c4] = val;
    }
    // k/v halo tiles: 144 px * 16 float4 each
    for (int idx = tid; idx < 144*16; idx += 256) {
        int hp = idx >> 4, c4 = idx & 15;
        int yy = y0 + (hp/12) - 2, xx = x0 + (hp%12) - 2;
        float4 kv = make_float4(0.f,0.f,0.f,0.f);
        float4 vv = make_float4(0.f,0.f,0.f,0.f);
        if (yy >= 0 && yy < 128 && xx >= 0 && xx < 128) {
            size_t base = (((size_t)n << 14) + (yy << 7) + xx)*64;
            kv = ((const float4*)(xk + base))[c4];
            vv = ((const float4*)(xv + base))[c4];
        }
        ((float4*)(k_s + hp*68))[c4] = kv;
        ((float4*)(v_s + hp*68))[c4] = vv;
    }
    __syncthreads();

    int pix = tid >> 2, q = tid & 3;
    int py = pix >> 3, px = pix & 7;

    const float4* qp = (const float4*)(q_s + pix*68 + q*16);
    float4 a0 = qp[0], a1 = qp[1], a2 = qp[2], a3 = qp[3];

    float wgt[25];
    #pragma unroll
    for (int dy = 0; dy < 5; dy++)
        #pragma unroll
        for (int dx = 0; dx < 5; dx++) {
            int nb = (py+dy)*12 + (px+dx);
            const float4* kp = (const float4*)(k_s + nb*68 + q*16);
            float s = dot4(a0, kp[0]) + dot4(a1, kp[1]) + dot4(a2, kp[2]) + dot4(a3, kp[3]);
            s += __shfl_xor_sync(0xffffffffu, s, 1);
            s += __shfl_xor_sync(0xffffffffu, s, 2);
            wgt[dy*5+dx] = s;
        }

    float m = wgt[0];
    #pragma unroll
    for (int k2 = 1; k2 < 25; k2++) m = fmaxf(m, wgt[k2]);
    float ssum = 0.f;
    #pragma unroll
    for (int k2 = 0; k2 < 25; k2++) { wgt[k2] = __expf(wgt[k2] - m); ssum += wgt[k2]; }
    float inv = 1.f / ssum;

    float4 o0 = make_float4(0,0,0,0), o1 = o0, o2 = o0, o3 = o0;
    #pragma unroll
    for (int dy = 0; dy < 5; dy++)
        #pragma unroll
        for (int dx = 0; dx < 5; dx++) {
            int nb = (py+dy)*12 + (px+dx);
            float wk = wgt[dy*5+dx];
            const float4* vp = (const float4*)(v_s + nb*68 + q*16);
            float4 v0 = vp[0], v1 = vp[1], v2 = vp[2], v3 = vp[3];
            o0.x = fmaf(wk, v0.x, o0.x); o0.y = fmaf(wk, v0.y, o0.y);
            o0.z = fmaf(wk, v0.z, o0.z); o0.w = fmaf(wk, v0.w, o0.w);
            o1.x = fmaf(wk, v1.x, o1.x); o1.y = fmaf(wk, v1.y, o1.y);
            o1.z = fmaf(wk, v1.z, o1.z); o1.w = fmaf(wk, v1.w, o1.w);
            o2.x = fmaf(wk, v2.x, o2.x); o2.y = fmaf(wk, v2.y, o2.y);
            o2.z = fmaf(wk, v2.z, o2.z); o2.w = fmaf(wk, v2.w, o2.w);
            o3.x = fmaf(wk, v3.x, o3.x); o3.y = fmaf(wk, v3.y, o3.y);
            o3.z = fmaf(wk, v3.z, o3.z); o3.w = fmaf(wk, v3.w, o3.w);
        }

    size_t base = (((size_t)n << 14) + ((size_t)(y0+py) << 7) + (x0+px))*64 + q*16;
    float4* dst = (float4*)(out + base);
    dst[0] = make_float4(fmaxf(o0.x*inv,0.f), fmaxf(o0.y*inv,0.f), fmaxf(o0.z*inv,0.f), fmaxf(o0.w*inv,0.f));
    dst[1] = make_float4(fmaxf(o1.x*inv,0.f), fmaxf(o1.y*inv,0.f), fmaxf(o1.z*inv,0.f), fmaxf(o1.w*inv,0.f));
    dst[2] = make_float4(fmaxf(o2.x*inv,0.f), fmaxf(o2.y*inv,0.f), fmaxf(o2.z*inv,0.f), fmaxf(o2.w*inv,0.f));
    dst[3] = make_float4(fmaxf(o3.x*inv,0.f), fmaxf(o3.y*inv,0.f), fmaxf(o3.z*inv,0.f), fmaxf(o3.w*inv,0.f));
}

// ---------------------------------------------------------------------------
// conv_out + residual: h NHWC -> conv3x3 (64->3) -> + x -> out NCHW
// thread = 1 pixel, 3 outputs.
// ---------------------------------------------------------------------------
__global__ __launch_bounds__(256) void conv_out_k(const float* __restrict__ h,
                                                  const float* __restrict__ w,
                                                  const float* __restrict__ xin,
                                                  float* __restrict__ out) {
    __shared__ float ws[9*192];   // [tap][o][c]
    int tid = threadIdx.x;
    for (int idx = tid; idx < 1728; idx += 256) {
        int tap = idx / 192, r = idx % 192, o = r >> 6, c = r & 63;
        ws[idx] = w[(o*64 + c)*9 + tap];
    }
    __syncthreads();

    int pix = blockIdx.x*256 + tid;
    int n = pix >> 14, rem = pix & 16383, y = rem >> 7, xx = rem & 127;

    float acc0 = 0.f, acc1 = 0.f, acc2 = 0.f;
    #pragma unroll
    for (int dy = 0; dy < 3; dy++) {
        int yy = y + dy - 1;
        if (yy < 0 || yy > 127) continue;
        #pragma unroll
        for (int dx = 0; dx < 3; dx++) {
            int xv = xx + dx - 1;
            if (xv < 0 || xv > 127) continue;
            int tap = dy*3 + dx;
            const float4* hp = (const float4*)(h + (((size_t)n << 14) + (yy << 7) + xv)*64);
            const float* wp = ws + tap*192;
            #pragma unroll
            for (int c4 = 0; c4 < 16; c4++) {
                float4 hv = hp[c4];
                float4 w0 = ((const float4*)(wp      ))[c4];
                float4 w1 = ((const float4*)(wp +  64))[c4];
                float4 w2 = ((const float4*)(wp + 128))[c4];
                acc0 += dot4(hv, w0);
                acc1 += dot4(hv, w1);
                acc2 += dot4(hv, w2);
            }
        }
    }
    int po = (y << 7) + xx;
    out[((n*3 + 0) << 14) + po] = acc0 + xin[((n*3 + 0) << 14) + po];
    out[((n*3 + 1) << 14) + po] = acc1 + xin[((n*3 + 1) << 14) + po];
    out[((n*3 + 2) << 14) + po] = acc2 + xin[((n*3 + 2) << 14) + po];
}

// ---------------------------------------------------------------------------
extern "C" void kernel_launch(void* const* d_in, const int* in_sizes, int n_in,
                              void* d_out, int out_size) {
    const float* x       = (const float*)d_in[0];
    const float* conv_in = (const float*)d_in[1];
    const float* W[9];
    for (int i = 0; i < 9; i++) W[i] = (const float*)d_in[2 + i];
    const float* conv_out = (const float*)d_in[11];
    float* out = (float*)d_out;

    float *A, *B, *Q, *K, *V;
    cudaGetSymbolAddress((void**)&A, g_bufA);
    cudaGetSymbolAddress((void**)&B, g_bufB);
    cudaGetSymbolAddress((void**)&Q, g_q);
    cudaGetSymbolAddress((void**)&K, g_k);
    cudaGetSymbolAddress((void**)&V, g_v);

    size_t qkv_smem  = (size_t)(64*64 + 64*192) * sizeof(float);        // 64 KB
    size_t attn_smem = (size_t)(64*68 + 2*144*68) * sizeof(float);      // ~93.5 KB
    cudaFuncSetAttribute(qkv_k,  cudaFuncAttributeMaxDynamicSharedMemorySize, (int)qkv_smem);
    cudaFuncSetAttribute(attn_k, cudaFuncAttributeMaxDynamicSharedMemorySize, (int)attn_smem);

    conv_in_k<<<NPIX/64, 256>>>(x, conv_in, A);

    float* hin = A; float* hout = B;
    for (int l = 0; l < 3; l++) {
        qkv_k<<<NPIX/64, 256, qkv_smem>>>(hin, W[3*l], W[3*l+1], W[3*l+2], Q, K, V);
        attn_k<<<dim3(16,16,8), 256, attn_smem>>>(Q, K, V, hout);
        float* t = hin; hin = hout; hout = t;
    }

    conv_out_k<<<NPIX/256, 256>>>(hin, conv_out, x, out);
}

// round 2
// speedup vs baseline: 1.6322x; 1.6322x over previous
#include <cuda_runtime.h>
#include <cuda_bf16.h>

#define NPIX (8*128*128)   // 131072 pixels
#define CCH  64

// Scratch (device globals). Activations NHWC: [n][y][x][c], c contiguous.
__device__ float g_bufA[(size_t)NPIX*CCH];
__device__ float g_bufB[(size_t)NPIX*CCH];
__device__ float g_q[(size_t)NPIX*CCH];
__device__ __nv_bfloat16 g_kb[(size_t)NPIX*CCH];
__device__ __nv_bfloat16 g_vb[(size_t)NPIX*CCH];

__device__ __forceinline__ float dot4(float4 a, float4 b) {
    return a.x*b.x + a.y*b.y + a.z*b.z + a.w*b.w;
}

// ---------------------------------------------------------------------------
// conv_in: x NCHW [8,3,128,128] -> relu(conv3x3) -> out NHWC
// ---------------------------------------------------------------------------
__global__ __launch_bounds__(256) void conv_in_k(const float* __restrict__ x,
                                                 const float* __restrict__ w,
                                                 float* __restrict__ out) {
    __shared__ float ws[64*27];
    int tid = threadIdx.x;
    for (int i = tid; i < 64*27; i += 256) ws[i] = w[i];
    __syncthreads();

    int pix = blockIdx.x*64 + (tid >> 2);
    int q   = tid & 3;
    int n = pix >> 14, rem = pix & 16383, y = rem >> 7, xx = rem & 127;

    float v[27];
    int t = 0;
    #pragma unroll
    for (int c = 0; c < 3; c++)
        #pragma unroll
        for (int dy = 0; dy < 3; dy++)
            #pragma unroll
            for (int dx = 0; dx < 3; dx++, t++) {
                int yy = y + dy - 1, xv = xx + dx - 1;
                bool ok = (yy >= 0) & (yy < 128) & (xv >= 0) & (xv < 128);
                v[t] = ok ? x[((n*3 + c) << 14) + (yy << 7) + xv] : 0.f;
            }

    float r[16];
    #pragma unroll
    for (int j = 0; j < 16; j++) {
        int o = q*16 + j;
        float acc = 0.f;
        #pragma unroll
        for (int tt = 0; tt < 27; tt++) acc = fmaf(v[tt], ws[o*27 + tt], acc);
        r[j] = fmaxf(acc, 0.f);
    }
    float4* dst = (float4*)(out + (size_t)pix*64 + q*16);
    dst[0] = make_float4(r[0], r[1], r[2], r[3]);
    dst[1] = make_float4(r[4], r[5], r[6], r[7]);
    dst[2] = make_float4(r[8], r[9], r[10], r[11]);
    dst[3] = make_float4(r[12], r[13], r[14], r[15]);
}

// ---------------------------------------------------------------------------
// qkv: fused triple 1x1. Thread tile 4px x (4q + 4k + 4v outputs).
// Weights in smem transposed [c][o], float4 loads both operands.
// q out fp32, k/v out bf16.
// ---------------------------------------------------------------------------
__global__ __launch_bounds__(256) void qkv_k(const float* __restrict__ in,
                                             const float* __restrict__ w1,
                                             const float* __restrict__ w2,
                                             const float* __restrict__ w3,
                                             float* __restrict__ qo,
                                             __nv_bfloat16* __restrict__ ko,
                                             __nv_bfloat16* __restrict__ vo) {
    extern __shared__ float sm[];
    float* in_s = sm;            // 64*64
    float* w_s  = sm + 64*64;    // 64*192, [c][o]
    int tid = threadIdx.x;
    size_t pix0 = (size_t)blockIdx.x * 64;

    const float4* src = (const float4*)(in + pix0*64);
    float4* d4 = (float4*)in_s;
    #pragma unroll
    for (int i = 0; i < 4; i++) d4[tid + 256*i] = src[tid + 256*i];

    for (int idx = tid; idx < 64*192; idx += 256) {
        int c = idx / 192, o = idx % 192;
        float val = (o < 64) ? w1[o*64 + c]
                  : (o < 128) ? w2[(o-64)*64 + c]
                              : w3[(o-128)*64 + c];
        w_s[c*192 + o] = val;
    }
    __syncthreads();

    int ox = tid & 15, py = tid >> 4;
    int o0 = ox*4, p0 = py*4;
    float acc[4][12];
    #pragma unroll
    for (int p = 0; p < 4; p++)
        #pragma unroll
        for (int j = 0; j < 12; j++) acc[p][j] = 0.f;

    #pragma unroll 4
    for (int c = 0; c < 64; c += 4) {
        float4 a[4];
        #pragma unroll
        for (int p = 0; p < 4; p++) a[p] = *(const float4*)&in_s[(p0+p)*64 + c];
        #pragma unroll
        for (int cc = 0; cc < 4; cc++) {
            float4 bq = *(const float4*)&w_s[(c+cc)*192 + o0];
            float4 bk = *(const float4*)&w_s[(c+cc)*192 + 64 + o0];
            float4 bv = *(const float4*)&w_s[(c+cc)*192 + 128 + o0];
            #pragma unroll
            for (int p = 0; p < 4; p++) {
                float av = (cc==0) ? a[p].x : (cc==1) ? a[p].y : (cc==2) ? a[p].z : a[p].w;
                acc[p][0] = fmaf(av, bq.x, acc[p][0]);
                acc[p][1] = fmaf(av, bq.y, acc[p][1]);
                acc[p][2] = fmaf(av, bq.z, acc[p][2]);
                acc[p][3] = fmaf(av, bq.w, acc[p][3]);
                acc[p][4] = fmaf(av, bk.x, acc[p][4]);
                acc[p][5] = fmaf(av, bk.y, acc[p][5]);
                acc[p][6] = fmaf(av, bk.z, acc[p][6]);
                acc[p][7] = fmaf(av, bk.w, acc[p][7]);
                acc[p][8]  = fmaf(av, bv.x, acc[p][8]);
                acc[p][9]  = fmaf(av, bv.y, acc[p][9]);
                acc[p][10] = fmaf(av, bv.z, acc[p][10]);
                acc[p][11] = fmaf(av, bv.w, acc[p][11]);
            }
        }
    }

    #pragma unroll
    for (int p = 0; p < 4; p++) {
        size_t pix = pix0 + p0 + p;
        *(float4*)&qo[pix*64 + o0] = make_float4(acc[p][0], acc[p][1], acc[p][2], acc[p][3]);
        __nv_bfloat162* kp = (__nv_bfloat162*)(ko + pix*64 + o0);
        kp[0] = __floats2bfloat162_rn(acc[p][4], acc[p][5]);
        kp[1] = __floats2bfloat162_rn(acc[p][6], acc[p][7]);
        __nv_bfloat162* vp = (__nv_bfloat162*)(vo + pix*64 + o0);
        vp[0] = __floats2bfloat162_rn(acc[p][8], acc[p][9]);
        vp[1] = __floats2bfloat162_rn(acc[p][10], acc[p][11]);
    }
}

// ---------------------------------------------------------------------------
// attn: 5x5 local attention + relu. q fp32 global->regs, k/v bf16 smem.
// Block = 8x8 tile, 4 thr/px (16ch each). Softmax logits staged in smem.
// ---------------------------------------------------------------------------
#define KROW 72   // bf16 elements per smem row (144B, 16B aligned, conflict-free)

__device__ __forceinline__ float bflo(unsigned u) { return __uint_as_float(u << 16); }
__device__ __forceinline__ float bfhi(unsigned u) { return __uint_as_float(u & 0xffff0000u); }

__global__ __launch_bounds__(256, 4) void attn_k(const float* __restrict__ xq,
                                                 const __nv_bfloat16* __restrict__ xk,
                                                 const __nv_bfloat16* __restrict__ xv,
                                                 float* __restrict__ out) {
    extern __shared__ char smc[];
    __nv_bfloat16* k_s = (__nv_bfloat16*)smc;            // 144 x KROW
    __nv_bfloat16* v_s = k_s + 144*KROW;                 // 144 x KROW
    float* wgt_s = (float*)(v_s + 144*KROW);             // 64 x 26
    int tid = threadIdx.x;
    int bx = blockIdx.x, by = blockIdx.y, n = blockIdx.z;
    int y0 = by*8, x0 = bx*8;

    // k/v halo 12x12, 8 uint4 (=64 bf16) per pixel
    for (int idx = tid; idx < 144*8; idx += 256) {
        int hp = idx >> 3, c8 = idx & 7;
        int yy = y0 + (hp/12) - 2, xx = x0 + (hp%12) - 2;
        uint4 kv = make_uint4(0,0,0,0), vv = make_uint4(0,0,0,0);
        if (yy >= 0 && yy < 128 && xx >= 0 && xx < 128) {
            size_t base = (((size_t)n << 14) + (yy << 7) + xx) * 8; // uint4 units
            kv = ((const uint4*)xk)[base + c8];
            vv = ((const uint4*)xv)[base + c8];
        }
        ((uint4*)(k_s + hp*KROW))[c8] = kv;
        ((uint4*)(v_s + hp*KROW))[c8] = vv;
    }
    __syncthreads();

    int pix = tid >> 2, q = tid & 3;
    int py = pix >> 3, px = pix & 7;

    // q from global
    float qr[16];
    {
        size_t gb = (((size_t)n << 14) + ((size_t)(y0+py) << 7) + (x0+px))*64 + q*16;
        const float4* qp = (const float4*)(xq + gb);
        #pragma unroll
        for (int i = 0; i < 4; i++) {
            float4 vq = qp[i];
            qr[4*i+0] = vq.x; qr[4*i+1] = vq.y; qr[4*i+2] = vq.z; qr[4*i+3] = vq.w;
        }
    }

    // similarity
    float m = -1e30f;
    #pragma unroll
    for (int dy = 0; dy < 5; dy++)
        #pragma unroll
        for (int dx = 0; dx < 5; dx++) {
            int nb = (py+dy)*12 + (px+dx);
            const uint4* kp = (const uint4*)(k_s + nb*KROW + q*16);
            uint4 ka = kp[0], kb = kp[1];
            float s = 0.f;
            s = fmaf(bflo(ka.x), qr[0],  s); s = fmaf(bfhi(ka.x), qr[1],  s);
            s = fmaf(bflo(ka.y), qr[2],  s); s = fmaf(bfhi(ka.y), qr[3],  s);
            s = fmaf(bflo(ka.z), qr[4],  s); s = fmaf(bfhi(ka.z), qr[5],  s);
            s = fmaf(bflo(ka.w), qr[6],  s); s = fmaf(bfhi(ka.w), qr[7],  s);
            s = fmaf(bflo(kb.x), qr[8],  s); s = fmaf(bfhi(kb.x), qr[9],  s);
            s = fmaf(bflo(kb.y), qr[10], s); s = fmaf(bfhi(kb.y), qr[11], s);
            s = fmaf(bflo(kb.z), qr[12], s); s = fmaf(bfhi(kb.z), qr[13], s);
            s = fmaf(bflo(kb.w), qr[14], s); s = fmaf(bfhi(kb.w), qr[15], s);
            s += __shfl_xor_sync(0xffffffffu, s, 1);
            s += __shfl_xor_sync(0xffffffffu, s, 2);
            wgt_s[pix*26 + dy*5 + dx] = s;     // all 4 quarters write same value
            m = fmaxf(m, s);
        }
    __syncwarp();

    // softmax: exp into smem, sum in regs
    float ssum = 0.f;
    #pragma unroll
    for (int t = 0; t < 25; t++) {
        float e = __expf(wgt_s[pix*26 + t] - m);
        ssum += e;
        wgt_s[pix*26 + t] = e;
    }
    float inv = 1.f / ssum;
    __syncwarp();

    // aggregation
    float o[16];
    #pragma unroll
    for (int i = 0; i < 16; i++) o[i] = 0.f;
    #pragma unroll
    for (int dy = 0; dy < 5; dy++)
        #pragma unroll
        for (int dx = 0; dx < 5; dx++) {
            int nb = (py+dy)*12 + (px+dx);
            float wk = wgt_s[pix*26 + dy*5 + dx];
            const uint4* vp = (const uint4*)(v_s + nb*KROW + q*16);
            uint4 va = vp[0], vb = vp[1];
            o[0]  = fmaf(wk, bflo(va.x), o[0]);  o[1]  = fmaf(wk, bfhi(va.x), o[1]);
            o[2]  = fmaf(wk, bflo(va.y), o[2]);  o[3]  = fmaf(wk, bfhi(va.y), o[3]);
            o[4]  = fmaf(wk, bflo(va.z), o[4]);  o[5]  = fmaf(wk, bfhi(va.z), o[5]);
            o[6]  = fmaf(wk, bflo(va.w), o[6]);  o[7]  = fmaf(wk, bfhi(va.w), o[7]);
            o[8]  = fmaf(wk, bflo(vb.x), o[8]);  o[9]  = fmaf(wk, bfhi(vb.x), o[9]);
            o[10] = fmaf(wk, bflo(vb.y), o[10]); o[11] = fmaf(wk, bfhi(vb.y), o[11]);
            o[12] = fmaf(wk, bflo(vb.z), o[12]); o[13] = fmaf(wk, bfhi(vb.z), o[13]);
            o[14] = fmaf(wk, bflo(vb.w), o[14]); o[15] = fmaf(wk, bfhi(vb.w), o[15]);
        }

    size_t base = (((size_t)n << 14) + ((size_t)(y0+py) << 7) + (x0+px))*64 + q*16;
    float4* dst = (float4*)(out + base);
    #pragma unroll
    for (int i = 0; i < 4; i++)
        dst[i] = make_float4(fmaxf(o[4*i+0]*inv, 0.f), fmaxf(o[4*i+1]*inv, 0.f),
                             fmaxf(o[4*i+2]*inv, 0.f), fmaxf(o[4*i+3]*inv, 0.f));
}

// ---------------------------------------------------------------------------
// conv_out + residual: h NHWC -> conv3x3 (64->3) + x -> NCHW
// ---------------------------------------------------------------------------
__global__ __launch_bounds__(256) void conv_out_k(const float* __restrict__ h,
                                                  const float* __restrict__ w,
                                                  const float* __restrict__ xin,
                                                  float* __restrict__ out) {
    __shared__ float ws[9*192];   // [tap][o][c]
    int tid = threadIdx.x;
    for (int idx = tid; idx < 1728; idx += 256) {
        int tap = idx / 192, r = idx % 192, o = r >> 6, c = r & 63;
        ws[idx] = w[(o*64 + c)*9 + tap];
    }
    __syncthreads();

    int pix = blockIdx.x*256 + tid;
    int n = pix >> 14, rem = pix & 16383, y = rem >> 7, xx = rem & 127;

    float acc0 = 0.f, acc1 = 0.f, acc2 = 0.f;
    #pragma unroll
    for (int dy = 0; dy < 3; dy++) {
        int yy = y + dy - 1;
        if (yy < 0 || yy > 127) continue;
        #pragma unroll
        for (int dx = 0; dx < 3; dx++) {
            int xv = xx + dx - 1;
            if (xv < 0 || xv > 127) continue;
            int tap = dy*3 + dx;
            const float4* hp = (const float4*)(h + (((size_t)n << 14) + (yy << 7) + xv)*64);
            const float* wp = ws + tap*192;
            #pragma unroll
            for (int c4 = 0; c4 < 16; c4++) {
                float4 hv = hp[c4];
                float4 w0 = ((const float4*)(wp      ))[c4];
                float4 w1 = ((const float4*)(wp +  64))[c4];
                float4 w2 = ((const float4*)(wp + 128))[c4];
                acc0 += dot4(hv, w0);
                acc1 += dot4(hv, w1);
                acc2 += dot4(hv, w2);
            }
        }
    }
    int po = (y << 7) + xx;
    out[((n*3 + 0) << 14) + po] = acc0 + xin[((n*3 + 0) << 14) + po];
    out[((n*3 + 1) << 14) + po] = acc1 + xin[((n*3 + 1) << 14) + po];
    out[((n*3 + 2) << 14) + po] = acc2 + xin[((n*3 + 2) << 14) + po];
}

// ---------------------------------------------------------------------------
extern "C" void kernel_launch(void* const* d_in, const int* in_sizes, int n_in,
                              void* d_out, int out_size) {
    const float* x       = (const float*)d_in[0];
    const float* conv_in = (const float*)d_in[1];
    const float* W[9];
    for (int i = 0; i < 9; i++) W[i] = (const float*)d_in[2 + i];
    const float* conv_out = (const float*)d_in[11];
    float* out = (float*)d_out;

    float *A, *B, *Q;
    __nv_bfloat16 *K, *V;
    cudaGetSymbolAddress((void**)&A, g_bufA);
    cudaGetSymbolAddress((void**)&B, g_bufB);
    cudaGetSymbolAddress((void**)&Q, g_q);
    cudaGetSymbolAddress((void**)&K, g_kb);
    cudaGetSymbolAddress((void**)&V, g_vb);

    size_t qkv_smem  = (size_t)(64*64 + 64*192) * sizeof(float);           // 64 KB
    size_t attn_smem = (size_t)(2*144*KROW) * sizeof(__nv_bfloat16)
                     + (size_t)(64*26) * sizeof(float);                    // ~47 KB
    cudaFuncSetAttribute(qkv_k,  cudaFuncAttributeMaxDynamicSharedMemorySize, (int)qkv_smem);
    cudaFuncSetAttribute(attn_k, cudaFuncAttributeMaxDynamicSharedMemorySize, (int)attn_smem);

    conv_in_k<<<NPIX/64, 256>>>(x, conv_in, A);

    float* hin = A; float* hout = B;
    for (int l = 0; l < 3; l++) {
        qkv_k<<<NPIX/64, 256, qkv_smem>>>(hin, W[3*l], W[3*l+1], W[3*l+2], Q, K, V);
        attn_k<<<dim3(16,16,8), 256, attn_smem>>>(Q, K, V, hout);
        float* t = hin; hin = hout; hout = t;
    }

    conv_out_k<<<NPIX/256, 256>>>(hin, conv_out, x, out);
}

// round 3
// speedup vs baseline: 3.1151x; 1.9085x over previous
#include <cuda_runtime.h>
#include <cuda_bf16.h>

#define NPIX (8*128*128)   // 131072 pixels
#define CCH  64

// Scratch (device globals). Activations NHWC: [n][y][x][c], c contiguous.
__device__ __nv_bfloat16 g_hb0[(size_t)NPIX*CCH];   // bf16 activations ping
__device__ __nv_bfloat16 g_hb1[(size_t)NPIX*CCH];   // bf16 activations pong
__device__ float g_hf[(size_t)NPIX*CCH];            // fp32 final activations
__device__ float g_q[(size_t)NPIX*CCH];
__device__ __nv_bfloat16 g_kb[(size_t)NPIX*CCH];
__device__ __nv_bfloat16 g_vb[(size_t)NPIX*CCH];

__device__ __forceinline__ float dot4(float4 a, float4 b) {
    return a.x*b.x + a.y*b.y + a.z*b.z + a.w*b.w;
}
__device__ __forceinline__ unsigned pack_bf(float a, float b) {
    __nv_bfloat162 h = __floats2bfloat162_rn(a, b);
    return *reinterpret_cast<unsigned*>(&h);
}

// ---------------------------------------------------------------------------
// conv_in: x NCHW [8,3,128,128] -> relu(conv3x3) -> out NHWC bf16
// ---------------------------------------------------------------------------
__global__ __launch_bounds__(256) void conv_in_k(const float* __restrict__ x,
                                                 const float* __restrict__ w,
                                                 __nv_bfloat16* __restrict__ out) {
    __shared__ float ws[64*27];
    int tid = threadIdx.x;
    for (int i = tid; i < 64*27; i += 256) ws[i] = w[i];
    __syncthreads();

    int pix = blockIdx.x*64 + (tid >> 2);
    int q   = tid & 3;
    int n = pix >> 14, rem = pix & 16383, y = rem >> 7, xx = rem & 127;

    float v[27];
    int t = 0;
    #pragma unroll
    for (int c = 0; c < 3; c++)
        #pragma unroll
        for (int dy = 0; dy < 3; dy++)
            #pragma unroll
            for (int dx = 0; dx < 3; dx++, t++) {
                int yy = y + dy - 1, xv = xx + dx - 1;
                bool ok = (yy >= 0) & (yy < 128) & (xv >= 0) & (xv < 128);
                v[t] = ok ? x[((n*3 + c) << 14) + (yy << 7) + xv] : 0.f;
            }

    float r[16];
    #pragma unroll
    for (int j = 0; j < 16; j++) {
        int o = q*16 + j;
        float acc = 0.f;
        #pragma unroll
        for (int tt = 0; tt < 27; tt++) acc = fmaf(v[tt], ws[o*27 + tt], acc);
        r[j] = fmaxf(acc, 0.f);
    }
    uint4 u0 = make_uint4(pack_bf(r[0],r[1]),  pack_bf(r[2],r[3]),
                          pack_bf(r[4],r[5]),  pack_bf(r[6],r[7]));
    uint4 u1 = make_uint4(pack_bf(r[8],r[9]),  pack_bf(r[10],r[11]),
                          pack_bf(r[12],r[13]),pack_bf(r[14],r[15]));
    uint4* dst = (uint4*)(out + (size_t)pix*64 + q*16);
    dst[0] = u0; dst[1] = u1;
}

// ---------------------------------------------------------------------------
// qkv: fused triple 1x1 via bf16 tensor-core mma (m16n8k16, fp32 accum).
// Block = 64 pixels x 192 outputs, K=64. 8 warps, warp tile 16px x 96 outs.
// A (act) and W staged in smem with 72-bf16 row stride (conflict-free frags).
// ---------------------------------------------------------------------------
__global__ __launch_bounds__(256) void qkv_k(const __nv_bfloat16* __restrict__ in,
                                             const float* __restrict__ w1,
                                             const float* __restrict__ w2,
                                             const float* __restrict__ w3,
                                             float* __restrict__ qo,
                                             __nv_bfloat16* __restrict__ ko,
                                             __nv_bfloat16* __restrict__ vo) {
    __shared__ __nv_bfloat16 a_s[64*72];
    __shared__ __nv_bfloat16 w_s[192*72];
    int tid = threadIdx.x;
    size_t pix0 = (size_t)blockIdx.x * 64;

    // A: 64 px x 64 ch bf16 -> a_s (row stride 72)
    {
        const uint4* src = (const uint4*)(in + pix0*64);   // 8 uint4 per pixel
        #pragma unroll
        for (int i = 0; i < 2; i++) {
            int idx = tid + 256*i;            // 0..511
            int row = idx >> 3, c8 = idx & 7;
            ((uint4*)(a_s + row*72))[0 + c8] = src[idx];
        }
    }
    // W: 192 x 64 fp32 -> bf16 w_s[o][k], row stride 72
    for (int idx = tid; idx < 192*16; idx += 256) {
        int o = idx >> 4, j = idx & 15;       // j: float4 index along k
        const float* wp = (o < 64) ? (w1 + o*64)
                        : (o < 128) ? (w2 + (o-64)*64)
                                    : (w3 + (o-128)*64);
        float4 f = ((const float4*)wp)[j];
        uint2 u = make_uint2(pack_bf(f.x, f.y), pack_bf(f.z, f.w));
        *(uint2*)(w_s + o*72 + j*4) = u;
    }
    __syncthreads();

    int lane = tid & 31, w = tid >> 5;
    int wm = (w >> 1) * 16;        // 4 m-groups
    int wn = (w & 1) * 96;         // 2 n-groups
    int lr = lane >> 2, lc = lane & 3;

    float c[12][4];
    #pragma unroll
    for (int t = 0; t < 12; t++)
        #pragma unroll
        for (int i = 0; i < 4; i++) c[t][i] = 0.f;

    #pragma unroll
    for (int ks = 0; ks < 4; ks++) {
        int k0 = ks*16;
        unsigned a0 = *(const unsigned*)&a_s[(wm+lr  )*72 + k0 + lc*2    ];
        unsigned a1 = *(const unsigned*)&a_s[(wm+lr+8)*72 + k0 + lc*2    ];
        unsigned a2 = *(const unsigned*)&a_s[(wm+lr  )*72 + k0 + lc*2 + 8];
        unsigned a3 = *(const unsigned*)&a_s[(wm+lr+8)*72 + k0 + lc*2 + 8];
        #pragma unroll
        for (int t = 0; t < 12; t++) {
            int bc = wn + t*8 + lr;
            unsigned b0 = *(const unsigned*)&w_s[bc*72 + k0 + lc*2    ];
            unsigned b1 = *(const unsigned*)&w_s[bc*72 + k0 + lc*2 + 8];
            asm volatile(
                "mma.sync.aligned.m16n8k16.row.col.f32.bf16.bf16.f32 "
                "{%0,%1,%2,%3}, {%4,%5,%6,%7}, {%8,%9}, {%0,%1,%2,%3};"
                : "+f"(c[t][0]), "+f"(c[t][1]), "+f"(c[t][2]), "+f"(c[t][3])
                : "r"(a0), "r"(a1), "r"(a2), "r"(a3), "r"(b0), "r"(b1));
        }
    }

    // Epilogue: rows = pixels, cols = outputs (q fp32 | k bf16 | v bf16)
    size_t pixA = pix0 + wm + lr;
    size_t pixB = pixA + 8;
    #pragma unroll
    for (int t = 0; t < 12; t++) {
        int n0 = wn + t*8 + lc*2;
        if (n0 < 64) {
            *(float2*)(qo + pixA*64 + n0) = make_float2(c[t][0], c[t][1]);
            *(float2*)(qo + pixB*64 + n0) = make_float2(c[t][2], c[t][3]);
        } else if (n0 < 128) {
            *(unsigned*)(ko + pixA*64 + n0 - 64) = pack_bf(c[t][0], c[t][1]);
            *(unsigned*)(ko + pixB*64 + n0 - 64) = pack_bf(c[t][2], c[t][3]);
        } else {
            *(unsigned*)(vo + pixA*64 + n0 - 128) = pack_bf(c[t][0], c[t][1]);
            *(unsigned*)(vo + pixB*64 + n0 - 128) = pack_bf(c[t][2], c[t][3]);
        }
    }
}

// ---------------------------------------------------------------------------
// attn: 5x5 local attention + relu. q fp32 global->regs, k/v bf16 smem.
// Output: bf16 (intermediate layers) or fp32 (last layer) via template.
// ---------------------------------------------------------------------------
#define KROW 72

__device__ __forceinline__ float bflo(unsigned u) { return __uint_as_float(u << 16); }
__device__ __forceinline__ float bfhi(unsigned u) { return __uint_as_float(u & 0xffff0000u); }

template<bool BF16OUT>
__global__ __launch_bounds__(256, 4) void attn_k(const float* __restrict__ xq,
                                                 const __nv_bfloat16* __restrict__ xk,
                                                 const __nv_bfloat16* __restrict__ xv,
                                                 float* __restrict__ outf,
                                                 __nv_bfloat16* __restrict__ outb) {
    extern __shared__ char smc[];
    __nv_bfloat16* k_s = (__nv_bfloat16*)smc;            // 144 x KROW
    __nv_bfloat16* v_s = k_s + 144*KROW;                 // 144 x KROW
    float* wgt_s = (float*)(v_s + 144*KROW);             // 64 x 26
    int tid = threadIdx.x;
    int bx = blockIdx.x, by = blockIdx.y, n = blockIdx.z;
    int y0 = by*8, x0 = bx*8;

    for (int idx = tid; idx < 144*8; idx += 256) {
        int hp = idx >> 3, c8 = idx & 7;
        int yy = y0 + (hp/12) - 2, xx = x0 + (hp%12) - 2;
        uint4 kv = make_uint4(0,0,0,0), vv = make_uint4(0,0,0,0);
        if (yy >= 0 && yy < 128 && xx >= 0 && xx < 128) {
            size_t base = (((size_t)n << 14) + (yy << 7) + xx) * 8;
            kv = ((const uint4*)xk)[base + c8];
            vv = ((const uint4*)xv)[base + c8];
        }
        ((uint4*)(k_s + hp*KROW))[c8] = kv;
        ((uint4*)(v_s + hp*KROW))[c8] = vv;
    }
    __syncthreads();

    int pix = tid >> 2, q = tid & 3;
    int py = pix >> 3, px = pix & 7;

    float qr[16];
    {
        size_t gb = (((size_t)n << 14) + ((size_t)(y0+py) << 7) + (x0+px))*64 + q*16;
        const float4* qp = (const float4*)(xq + gb);
        #pragma unroll
        for (int i = 0; i < 4; i++) {
            float4 vq = qp[i];
            qr[4*i+0] = vq.x; qr[4*i+1] = vq.y; qr[4*i+2] = vq.z; qr[4*i+3] = vq.w;
        }
    }

    float m = -1e30f;
    #pragma unroll
    for (int dy = 0; dy < 5; dy++)
        #pragma unroll
        for (int dx = 0; dx < 5; dx++) {
            int nb = (py+dy)*12 + (px+dx);
            const uint4* kp = (const uint4*)(k_s + nb*KROW + q*16);
            uint4 ka = kp[0], kb = kp[1];
            float s = 0.f;
            s = fmaf(bflo(ka.x), qr[0],  s); s = fmaf(bfhi(ka.x), qr[1],  s);
            s = fmaf(bflo(ka.y), qr[2],  s); s = fmaf(bfhi(ka.y), qr[3],  s);
            s = fmaf(bflo(ka.z), qr[4],  s); s = fmaf(bfhi(ka.z), qr[5],  s);
            s = fmaf(bflo(ka.w), qr[6],  s); s = fmaf(bfhi(ka.w), qr[7],  s);
            s = fmaf(bflo(kb.x), qr[8],  s); s = fmaf(bfhi(kb.x), qr[9],  s);
            s = fmaf(bflo(kb.y), qr[10], s); s = fmaf(bfhi(kb.y), qr[11], s);
            s = fmaf(bflo(kb.z), qr[12], s); s = fmaf(bfhi(kb.z), qr[13], s);
            s = fmaf(bflo(kb.w), qr[14], s); s = fmaf(bfhi(kb.w), qr[15], s);
            s += __shfl_xor_sync(0xffffffffu, s, 1);
            s += __shfl_xor_sync(0xffffffffu, s, 2);
            wgt_s[pix*26 + dy*5 + dx] = s;
            m = fmaxf(m, s);
        }
    __syncwarp();

    float ssum = 0.f;
    #pragma unroll
    for (int t = 0; t < 25; t++) {
        float e = __expf(wgt_s[pix*26 + t] - m);
        ssum += e;
        wgt_s[pix*26 + t] = e;
    }
    float inv = 1.f / ssum;
    __syncwarp();

    float o[16];
    #pragma unroll
    for (int i = 0; i < 16; i++) o[i] = 0.f;
    #pragma unroll
    for (int dy = 0; dy < 5; dy++)
        #pragma unroll
        for (int dx = 0; dx < 5; dx++) {
            int nb = (py+dy)*12 + (px+dx);
            float wk = wgt_s[pix*26 + dy*5 + dx];
            const uint4* vp = (const uint4*)(v_s + nb*KROW + q*16);
            uint4 va = vp[0], vb = vp[1];
            o[0]  = fmaf(wk, bflo(va.x), o[0]);  o[1]  = fmaf(wk, bfhi(va.x), o[1]);
            o[2]  = fmaf(wk, bflo(va.y), o[2]);  o[3]  = fmaf(wk, bfhi(va.y), o[3]);
            o[4]  = fmaf(wk, bflo(va.z), o[4]);  o[5]  = fmaf(wk, bfhi(va.z), o[5]);
            o[6]  = fmaf(wk, bflo(va.w), o[6]);  o[7]  = fmaf(wk, bfhi(va.w), o[7]);
            o[8]  = fmaf(wk, bflo(vb.x), o[8]);  o[9]  = fmaf(wk, bfhi(vb.x), o[9]);
            o[10] = fmaf(wk, bflo(vb.y), o[10]); o[11] = fmaf(wk, bfhi(vb.y), o[11]);
            o[12] = fmaf(wk, bflo(vb.z), o[12]); o[13] = fmaf(wk, bfhi(vb.z), o[13]);
            o[14] = fmaf(wk, bflo(vb.w), o[14]); o[15] = fmaf(wk, bfhi(vb.w), o[15]);
        }

    size_t base = (((size_t)n << 14) + ((size_t)(y0+py) << 7) + (x0+px))*64 + q*16;
    if (BF16OUT) {
        uint4 u0 = make_uint4(pack_bf(fmaxf(o[0]*inv,0.f),  fmaxf(o[1]*inv,0.f)),
                              pack_bf(fmaxf(o[2]*inv,0.f),  fmaxf(o[3]*inv,0.f)),
                              pack_bf(fmaxf(o[4]*inv,0.f),  fmaxf(o[5]*inv,0.f)),
                              pack_bf(fmaxf(o[6]*inv,0.f),  fmaxf(o[7]*inv,0.f)));
        uint4 u1 = make_uint4(pack_bf(fmaxf(o[8]*inv,0.f),  fmaxf(o[9]*inv,0.f)),
                              pack_bf(fmaxf(o[10]*inv,0.f), fmaxf(o[11]*inv,0.f)),
                              pack_bf(fmaxf(o[12]*inv,0.f), fmaxf(o[13]*inv,0.f)),
                              pack_bf(fmaxf(o[14]*inv,0.f), fmaxf(o[15]*inv,0.f)));
        uint4* dst = (uint4*)(outb + base);
        dst[0] = u0; dst[1] = u1;
    } else {
        float4* dst = (float4*)(outf + base);
        #pragma unroll
        for (int i = 0; i < 4; i++)
            dst[i] = make_float4(fmaxf(o[4*i+0]*inv, 0.f), fmaxf(o[4*i+1]*inv, 0.f),
                                 fmaxf(o[4*i+2]*inv, 0.f), fmaxf(o[4*i+3]*inv, 0.f));
    }
}

// ---------------------------------------------------------------------------
// conv_out + residual: h NHWC fp32 -> conv3x3 (64->3) + x -> NCHW
// ---------------------------------------------------------------------------
__global__ __launch_bounds__(256) void conv_out_k(const float* __restrict__ h,
                                                  const float* __restrict__ w,
                                                  const float* __restrict__ xin,
                                                  float* __restrict__ out) {
    __shared__ float ws[9*192];   // [tap][o][c]
    int tid = threadIdx.x;
    for (int idx = tid; idx < 1728; idx += 256) {
        int tap = idx / 192, r = idx % 192, o = r >> 6, c = r & 63;
        ws[idx] = w[(o*64 + c)*9 + tap];
    }
    __syncthreads();

    int pix = blockIdx.x*256 + tid;
    int n = pix >> 14, rem = pix & 16383, y = rem >> 7, xx = rem & 127;

    float acc0 = 0.f, acc1 = 0.f, acc2 = 0.f;
    #pragma unroll
    for (int dy = 0; dy < 3; dy++) {
        int yy = y + dy - 1;
        if (yy < 0 || yy > 127) continue;
        #pragma unroll
        for (int dx = 0; dx < 3; dx++) {
            int xv = xx + dx - 1;
            if (xv < 0 || xv > 127) continue;
            int tap = dy*3 + dx;
            const float4* hp = (const float4*)(h + (((size_t)n << 14) + (yy << 7) + xv)*64);
            const float* wp = ws + tap*192;
            #pragma unroll
            for (int c4 = 0; c4 < 16; c4++) {
                float4 hv = hp[c4];
                float4 w0 = ((const float4*)(wp      ))[c4];
                float4 w1 = ((const float4*)(wp +  64))[c4];
                float4 w2 = ((const float4*)(wp + 128))[c4];
                acc0 += dot4(hv, w0);
                acc1 += dot4(hv, w1);
                acc2 += dot4(hv, w2);
            }
        }
    }
    int po = (y << 7) + xx;
    out[((n*3 + 0) << 14) + po] = acc0 + xin[((n*3 + 0) << 14) + po];
    out[((n*3 + 1) << 14) + po] = acc1 + xin[((n*3 + 1) << 14) + po];
    out[((n*3 + 2) << 14) + po] = acc2 + xin[((n*3 + 2) << 14) + po];
}

// ---------------------------------------------------------------------------
extern "C" void kernel_launch(void* const* d_in, const int* in_sizes, int n_in,
                              void* d_out, int out_size) {
    const float* x       = (const float*)d_in[0];
    const float* conv_in = (const float*)d_in[1];
    const float* W[9];
    for (int i = 0; i < 9; i++) W[i] = (const float*)d_in[2 + i];
    const float* conv_out = (const float*)d_in[11];
    float* out = (float*)d_out;

    __nv_bfloat16 *H0, *H1, *K, *V;
    float *HF, *Q;
    cudaGetSymbolAddress((void**)&H0, g_hb0);
    cudaGetSymbolAddress((void**)&H1, g_hb1);
    cudaGetSymbolAddress((void**)&HF, g_hf);
    cudaGetSymbolAddress((void**)&Q,  g_q);
    cudaGetSymbolAddress((void**)&K,  g_kb);
    cudaGetSymbolAddress((void**)&V,  g_vb);

    size_t attn_smem = (size_t)(2*144*KROW) * sizeof(__nv_bfloat16)
                     + (size_t)(64*26) * sizeof(float);                    // ~47 KB
    cudaFuncSetAttribute(attn_k<true>,  cudaFuncAttributeMaxDynamicSharedMemorySize, (int)attn_smem);
    cudaFuncSetAttribute(attn_k<false>, cudaFuncAttributeMaxDynamicSharedMemorySize, (int)attn_smem);

    conv_in_k<<<NPIX/64, 256>>>(x, conv_in, H0);

    // layer 0: H0 -> H1 (bf16)
    qkv_k<<<NPIX/64, 256>>>(H0, W[0], W[1], W[2], Q, K, V);
    attn_k<true><<<dim3(16,16,8), 256, attn_smem>>>(Q, K, V, nullptr, H1);
    // layer 1: H1 -> H0 (bf16)
    qkv_k<<<NPIX/64, 256>>>(H1, W[3], W[4], W[5], Q, K, V);
    attn_k<true><<<dim3(16,16,8), 256, attn_smem>>>(Q, K, V, nullptr, H0);
    // layer 2: H0 -> HF (fp32)
    qkv_k<<<NPIX/64, 256>>>(H0, W[6], W[7], W[8], Q, K, V);
    attn_k<false><<<dim3(16,16,8), 256, attn_smem>>>(Q, K, V, HF, nullptr);

    conv_out_k<<<NPIX/256, 256>>>(HF, conv_out, x, out);
}